// round 16
// baseline (speedup 1.0000x reference)
#include <cuda_runtime.h>
#include <cuda_bf16.h>

typedef unsigned long long ull;

#define Bsz 64
#define Ssz 512
#define Dsz 256
#define Hsz 512
#define ROWS (Bsz * Ssz)   /* 32768 */
#define GXN  (4 * Hsz)     /* 2048  */
#define NBLK 128           /* persistent CTAs (all resident on 148 SMs) */

// ---------------------------------------------------------------------------
// Static device scratch
// ---------------------------------------------------------------------------
__device__ float g_gxq[(size_t)ROWS * GXN];   // [b*512+t][j*4+gate]
__device__ float g_hs[(size_t)ROWS * Hsz];    // [b*512+t][j]
__device__ float g_c[Bsz * Hsz];
__device__ float g_bq[GXN];
// per-bgroup barrier state (separate 128B lines)
__device__ unsigned g_cnt2[2 * 32];
__device__ unsigned g_gen2[2 * 32];
// bf16 split operands for the tensor-core input GEMM
__device__ __nv_bfloat16 g_xhi[(size_t)ROWS * Dsz];
__device__ __nv_bfloat16 g_xlo[(size_t)ROWS * Dsz];
__device__ __nv_bfloat16 g_Wthi[(size_t)GXN * Dsz];   // [n][k] (n = j*4+gate)
__device__ __nv_bfloat16 g_Wtlo[(size_t)GXN * Dsz];
// bf16 split U for the HMMA recurrence: [jg(64)][n32(32)][k(512)], n32 = j8*4+g
__device__ __nv_bfloat16 g_Ubhi[64 * 32 * 512];
__device__ __nv_bfloat16 g_Ublo[64 * 32 * 512];
// bf16 split h, double-buffered: [buf][b(64)][j(512)]
__device__ __nv_bfloat16 g_hbhi[2][Bsz * Hsz];
__device__ __nv_bfloat16 g_hblo[2][Bsz * Hsz];

// ---------------------------------------------------------------------------
// helpers
// ---------------------------------------------------------------------------
__device__ __forceinline__ unsigned ld_acq(const unsigned* p) {
    unsigned v; asm volatile("ld.acquire.gpu.b32 %0, [%1];" : "=r"(v) : "l"(p)); return v;
}
__device__ __forceinline__ float sigmoidf_(float x) { return 1.0f / (1.0f + __expf(-x)); }
__device__ __forceinline__ float tanhf_(float x)    { return 1.0f - 2.0f / (__expf(2.0f * x) + 1.0f); }

__device__ __forceinline__ unsigned smem_u32(const void* p) {
    unsigned a;
    asm("{ .reg .u64 t; cvta.to.shared.u64 t, %1; cvt.u32.u64 %0, t; }" : "=r"(a) : "l"(p));
    return a;
}
__device__ __forceinline__ void ldsm4(unsigned& r0, unsigned& r1, unsigned& r2, unsigned& r3,
                                      unsigned addr) {
    asm volatile("ldmatrix.sync.aligned.m8n8.x4.shared.b16 {%0,%1,%2,%3}, [%4];"
                 : "=r"(r0), "=r"(r1), "=r"(r2), "=r"(r3) : "r"(addr));
}
__device__ __forceinline__ void ldsm2(unsigned& r0, unsigned& r1, unsigned addr) {
    asm volatile("ldmatrix.sync.aligned.m8n8.x2.shared.b16 {%0,%1}, [%2];"
                 : "=r"(r0), "=r"(r1) : "r"(addr));
}
__device__ __forceinline__ void mma_bf16(float& c0, float& c1, float& c2, float& c3,
                                         unsigned a0, unsigned a1, unsigned a2, unsigned a3,
                                         unsigned b0, unsigned b1) {
    asm volatile("mma.sync.aligned.m16n8k16.row.col.f32.bf16.bf16.f32 "
                 "{%0,%1,%2,%3}, {%4,%5,%6,%7}, {%8,%9}, {%0,%1,%2,%3};"
                 : "+f"(c0), "+f"(c1), "+f"(c2), "+f"(c3)
                 : "r"(a0), "r"(a1), "r"(a2), "r"(a3), "r"(b0), "r"(b1));
}

// ---------------------------------------------------------------------------
// Launch 0: split x into bf16 hi/lo (halves GEMM A-side L2 traffic)
// ---------------------------------------------------------------------------
__global__ void splitx_kernel(const float* __restrict__ x) {
    size_t i = (size_t)blockIdx.x * blockDim.x + threadIdx.x;   // ROWS*Dsz
    float v = x[i];
    __nv_bfloat16 hi = __float2bfloat16(v);
    g_xhi[i] = hi;
    g_xlo[i] = __float2bfloat16(v - __bfloat162float(hi));
}

// ---------------------------------------------------------------------------
// Launch 1: fused prep
//   blocks [0,4096):      U -> bf16 hi/lo [jg][n32][k]
//   blocks [4096,6144):   W -> transposed bf16 hi/lo + bias
//   blocks [6144,6400):   zero h0 (bf16 bufs) + barrier counters
// ---------------------------------------------------------------------------
__global__ void prep_kernel(const float* __restrict__ Wf, const float* __restrict__ Wi,
                            const float* __restrict__ Wo, const float* __restrict__ Wc,
                            const float* __restrict__ bf, const float* __restrict__ bi,
                            const float* __restrict__ bo, const float* __restrict__ bc,
                            const float* __restrict__ Uf, const float* __restrict__ Ui,
                            const float* __restrict__ Uo, const float* __restrict__ Uc) {
    const int blk = blockIdx.x;
    const int tid = threadIdx.x;
    if (blk < 4096) {
        int idx = blk * 256 + tid;                 // 0..1048575 = jg*32n*512k
        int k   = idx & 511;
        int n32 = (idx >> 9) & 31;
        int jg  = idx >> 14;
        int j   = jg * 8 + (n32 >> 2);
        int g   = n32 & 3;
        const float* Ug = (g == 0) ? Uf : (g == 1) ? Ui : (g == 2) ? Uo : Uc;
        float v = Ug[(size_t)k * Hsz + j];
        __nv_bfloat16 hi = __float2bfloat16(v);
        g_Ubhi[idx] = hi;
        g_Ublo[idx] = __float2bfloat16(v - __bfloat162float(hi));
    } else if (blk < 6144) {
        int idx = (blk - 4096) * 256 + tid;        // 0..524287
        int n = idx >> 8;
        int k = idx & 255;
        int j = n >> 2, g = n & 3;
        const float* Wg = (g == 0) ? Wf : (g == 1) ? Wi : (g == 2) ? Wo : Wc;
        float v = Wg[(size_t)k * Hsz + j];
        __nv_bfloat16 hi = __float2bfloat16(v);
        g_Wthi[(size_t)n * Dsz + k] = hi;
        g_Wtlo[(size_t)n * Dsz + k] = __float2bfloat16(v - __bfloat162float(hi));
        if (k == 0) {
            const float* bg = (g == 0) ? bf : (g == 1) ? bi : (g == 2) ? bo : bc;
            g_bq[n] = bg[j];
        }
    } else {
        int i = (blk - 6144) * 256 + tid;          // 0..65535
        if (i < Bsz * Hsz) {
            g_hbhi[0][i] = __float2bfloat16(0.0f);
            g_hblo[0][i] = __float2bfloat16(0.0f);
        }
        if (i < 2) { g_cnt2[i * 32] = 0u; g_gen2[i * 32] = 0u; }
    }
}

// ---------------------------------------------------------------------------
// Launch 2: mma.sync bf16 split-precision input GEMM (R14 proven version,
//           reads pre-split bf16 x)
// ---------------------------------------------------------------------------
#define SB_ST   264
#define SA_ST   40
#define SB_HI   0
#define SB_LO   (64 * SB_ST * 2)
#define SA_HI   (2 * 64 * SB_ST * 2)
#define SA_LO   (SA_HI + 128 * SA_ST * 2)
#define GT_SMEM (SA_LO + 128 * SA_ST * 2)     /* 88064 */

__global__ void __launch_bounds__(256, 2)
gemm_tc_kernel() {
    extern __shared__ char smem[];
    const unsigned sbase = smem_u32(smem);

    const int tid  = threadIdx.x;
    const int lane = tid & 31;
    const int wid  = tid >> 5;
    const int wm   = wid & 3;
    const int wn   = wid >> 2;
    const int m0w  = wm * 32;
    const int n0w  = wn * 32;
    const int n0   = blockIdx.x * 64;
    const int r0   = blockIdx.y * 128;

    #pragma unroll
    for (int r = 0; r < 8; r++) {
        int v = r * 256 + tid;
        int row = v >> 5, cu = v & 31;
        size_t src = (size_t)(n0 + row) * Dsz + cu * 8;
        *(uint4*)(smem + SB_HI + (row * SB_ST + cu * 8) * 2) = *(const uint4*)&g_Wthi[src];
        *(uint4*)(smem + SB_LO + (row * SB_ST + cu * 8) * 2) = *(const uint4*)&g_Wtlo[src];
    }

    float c[2][4][4];
    #pragma unroll
    for (int mi = 0; mi < 2; mi++)
        #pragma unroll
        for (int ni = 0; ni < 4; ni++)
            #pragma unroll
            for (int e = 0; e < 4; e++) c[mi][ni][e] = 0.0f;

    const int aRow  = lane & 15;
    const int aKoff = (lane >> 4) * 8;
    const int bSel  = lane >> 3;
    const int bRow  = (bSel >> 1) * 8 + (lane & 7);
    const int bKoff = (bSel & 1) * 8;

    for (int kc = 0; kc < 8; kc++) {
        __syncthreads();
        #pragma unroll
        for (int r = 0; r < 2; r++) {
            int v = r * 256 + tid;
            int row = v >> 2, cu = v & 3;
            size_t src = (size_t)(r0 + row) * Dsz + kc * 32 + cu * 8;
            *(uint4*)(smem + SA_HI + (row * SA_ST + cu * 8) * 2) = *(const uint4*)&g_xhi[src];
            *(uint4*)(smem + SA_LO + (row * SA_ST + cu * 8) * 2) = *(const uint4*)&g_xlo[src];
        }
        __syncthreads();

        #pragma unroll
        for (int ks = 0; ks < 2; ks++) {
            const int kchunk = ks * 16;
            const int kglob  = kc * 32 + kchunk;

            unsigned ah[2][4], al[2][4];
            #pragma unroll
            for (int mi = 0; mi < 2; mi++) {
                unsigned off = (unsigned)((m0w + mi * 16 + aRow) * SA_ST + kchunk + aKoff) * 2;
                ldsm4(ah[mi][0], ah[mi][1], ah[mi][2], ah[mi][3], sbase + SA_HI + off);
                ldsm4(al[mi][0], al[mi][1], al[mi][2], al[mi][3], sbase + SA_LO + off);
            }
            unsigned bh[4][2], bl[4][2];
            #pragma unroll
            for (int half = 0; half < 2; half++) {
                unsigned off = (unsigned)((n0w + half * 16 + bRow) * SB_ST + kglob + bKoff) * 2;
                ldsm4(bh[half * 2][0], bh[half * 2][1], bh[half * 2 + 1][0], bh[half * 2 + 1][1],
                      sbase + SB_HI + off);
                ldsm4(bl[half * 2][0], bl[half * 2][1], bl[half * 2 + 1][0], bl[half * 2 + 1][1],
                      sbase + SB_LO + off);
            }

            #pragma unroll
            for (int mi = 0; mi < 2; mi++)
                #pragma unroll
                for (int ni = 0; ni < 4; ni++) {
                    float* cc = c[mi][ni];
                    mma_bf16(cc[0], cc[1], cc[2], cc[3],
                             ah[mi][0], ah[mi][1], ah[mi][2], ah[mi][3],
                             bh[ni][0], bh[ni][1]);
                    mma_bf16(cc[0], cc[1], cc[2], cc[3],
                             ah[mi][0], ah[mi][1], ah[mi][2], ah[mi][3],
                             bl[ni][0], bl[ni][1]);
                    mma_bf16(cc[0], cc[1], cc[2], cc[3],
                             al[mi][0], al[mi][1], al[mi][2], al[mi][3],
                             bh[ni][0], bh[ni][1]);
                }
        }
    }

    const int crow = lane >> 2;
    const int ccol = (lane & 3) * 2;
    #pragma unroll
    for (int mi = 0; mi < 2; mi++) {
        #pragma unroll
        for (int ni = 0; ni < 4; ni++) {
            int col = n0 + n0w + ni * 8 + ccol;
            float2 bb = *(const float2*)&g_bq[col];
            int m1 = r0 + m0w + mi * 16 + crow;
            float2 o0; o0.x = c[mi][ni][0] + bb.x; o0.y = c[mi][ni][1] + bb.y;
            float2 o1; o1.x = c[mi][ni][2] + bb.x; o1.y = c[mi][ni][3] + bb.y;
            *(float2*)&g_gxq[(size_t)m1 * GXN + col] = o0;
            *(float2*)&g_gxq[(size_t)(m1 + 8) * GXN + col] = o1;
        }
    }
}

// ---------------------------------------------------------------------------
// Launch 3 (PROFILED): persistent HMMA LSTM recurrence
//   Per-bgroup barriers; storer-only fence; warp-parallel gen polling
//   (lane0 poll + __syncwarp, no post-detect __syncthreads).
// ---------------------------------------------------------------------------
#define RN_ST    520                     /* bf16 per row (1040B stride) */
#define RN_SPLIT (32 * RN_ST * 2)        /* 33280 B per split */
#define RN_SU    0
#define RN_SH    (2 * RN_SPLIT)          /* 66560 */
#define RN_SRED  (4 * RN_SPLIT)          /* 133120 */
#define RN_RST   34                      /* f32 stride per m-row (even) */
#define RN_RSL   (32 * RN_RST)           /* 1088 floats per k-slice */
#define RN_SMEM  (RN_SRED + 4 * RN_RSL * 4)    /* 150528 */

__global__ void __launch_bounds__(512, 1)
recur_kernel() {
    extern __shared__ char smem[];
    const unsigned sbase = smem_u32(smem);
    float* sRedF = (float*)(smem + RN_SRED);

    const int tid  = threadIdx.x;
    const int lane = tid & 31;
    const int wid  = tid >> 5;
    const int ng   = wid & 3;            // n-group (8 n cols)
    const int ksl  = wid >> 2;           // k-slice (128 k)
    const int jg   = blockIdx.x >> 1;
    const int bg   = blockIdx.x & 1;

    unsigned* cnt = &g_cnt2[bg * 32];
    unsigned* gen = &g_gen2[bg * 32];

    // ---- load U slice (bf16 hi/lo) into SMEM once ----
    {
        const __nv_bfloat16* uh = &g_Ubhi[jg * 32 * 512];
        const __nv_bfloat16* ul = &g_Ublo[jg * 32 * 512];
        #pragma unroll
        for (int r = 0; r < 8; r++) {
            int v = r * 512 + tid;               // 0..4095 uint4 (both splits)
            int split = v >> 11;
            int w = v & 2047;
            int n = w >> 6, k8 = w & 63;
            const __nv_bfloat16* src = split ? ul : uh;
            *(uint4*)(smem + RN_SU + split * RN_SPLIT + n * (RN_ST * 2) + k8 * 16) =
                *(const uint4*)&src[n * 512 + k8 * 8];
        }
    }

    const int aRow  = lane & 15;
    const int aKoff = (lane >> 4) * 8;
    const int bRow  = lane & 7;
    const int bKoff = ((lane >> 3) & 1) * 8;

    const int eb  = tid & 31;
    const int ej8 = (tid >> 5) & 7;
    const int ejcol = jg * 8 + ej8;
    float cst = 0.0f;

    for (int t = 0; t < Ssz; t++) {
        const int rd = t & 1, wr = rd ^ 1;

        float4 gx;
        if (tid < 256)
            gx = *(const float4*)
                &g_gxq[(size_t)((bg * 32 + eb) * Ssz + t) * GXN + ejcol * 4];

        // ---- stage h (bf16 hi/lo) rows [bg*32, bg*32+32) ----
        {
            const __nv_bfloat16* hh = g_hbhi[rd];
            const __nv_bfloat16* hl = g_hblo[rd];
            #pragma unroll
            for (int r = 0; r < 8; r++) {
                int v = r * 512 + tid;
                int split = v >> 11;
                int w = v & 2047;
                int row = w >> 6, k8 = w & 63;
                const __nv_bfloat16* src = split ? hl : hh;
                uint4 d = __ldcg((const uint4*)&src[(bg * 32 + row) * Hsz + k8 * 8]);
                *(uint4*)(smem + RN_SH + split * RN_SPLIT + row * (RN_ST * 2) + k8 * 16) = d;
            }
        }
        __syncthreads();

        // ---- HMMA compute ----
        float c[2][4];
        #pragma unroll
        for (int mi = 0; mi < 2; mi++)
            #pragma unroll
            for (int e = 0; e < 4; e++) c[mi][e] = 0.0f;

        const int kbase = ksl * 128;
        #pragma unroll 2
        for (int kf = 0; kf < 8; kf++) {
            const int k = kbase + kf * 16;
            unsigned ah[2][4], al[2][4];
            #pragma unroll
            for (int mi = 0; mi < 2; mi++) {
                unsigned off = (unsigned)((mi * 16 + aRow) * (RN_ST * 2) + (k + aKoff) * 2);
                ldsm4(ah[mi][0], ah[mi][1], ah[mi][2], ah[mi][3],
                      sbase + RN_SH + off);
                ldsm4(al[mi][0], al[mi][1], al[mi][2], al[mi][3],
                      sbase + RN_SH + RN_SPLIT + off);
            }
            unsigned bh[2], bl[2];
            {
                unsigned off = (unsigned)((ng * 8 + bRow) * (RN_ST * 2) + (k + bKoff) * 2);
                ldsm2(bh[0], bh[1], sbase + RN_SU + off);
                ldsm2(bl[0], bl[1], sbase + RN_SU + RN_SPLIT + off);
            }
            #pragma unroll
            for (int mi = 0; mi < 2; mi++) {
                mma_bf16(c[mi][0], c[mi][1], c[mi][2], c[mi][3],
                         ah[mi][0], ah[mi][1], ah[mi][2], ah[mi][3], bh[0], bh[1]);
                mma_bf16(c[mi][0], c[mi][1], c[mi][2], c[mi][3],
                         ah[mi][0], ah[mi][1], ah[mi][2], ah[mi][3], bl[0], bl[1]);
                mma_bf16(c[mi][0], c[mi][1], c[mi][2], c[mi][3],
                         al[mi][0], al[mi][1], al[mi][2], al[mi][3], bh[0], bh[1]);
            }
        }

        // ---- write partials to sRed[ksl][m][RN_RST] ----
        {
            const int col = ng * 8 + (lane & 3) * 2;
            #pragma unroll
            for (int mi = 0; mi < 2; mi++) {
                int m = mi * 16 + (lane >> 2);
                float2 p0; p0.x = c[mi][0]; p0.y = c[mi][1];
                float2 p1; p1.x = c[mi][2]; p1.y = c[mi][3];
                *(float2*)&sRedF[ksl * RN_RSL + m * RN_RST + col]       = p0;
                *(float2*)&sRedF[ksl * RN_RSL + (m + 8) * RN_RST + col] = p1;
            }
        }
        __syncthreads();

        // ---- epilogue: 256 threads, one (b,j) cell each ----
        if (tid < 256) {
            float s[4];
            #pragma unroll
            for (int g = 0; g < 4; g++) {
                int cix = eb * RN_RST + ej8 * 4 + g;
                s[g] = sRedF[cix] + sRedF[RN_RSL + cix]
                     + sRedF[2 * RN_RSL + cix] + sRedF[3 * RN_RSL + cix];
            }
            float pf = gx.x + s[0];
            float pi = gx.y + s[1];
            float po = gx.z + s[2];
            float pc = gx.w + s[3];

            cst = sigmoidf_(pf) * cst + sigmoidf_(pi) * tanhf_(pc);
            float hn = sigmoidf_(po) * tanhf_(cst);

            int bglob = bg * 32 + eb;
            __nv_bfloat16 hhi = __float2bfloat16(hn);
            g_hbhi[wr][bglob * Hsz + ejcol] = hhi;
            g_hblo[wr][bglob * Hsz + ejcol] =
                __float2bfloat16(hn - __bfloat162float(hhi));
            g_hs[(size_t)(bglob * Ssz + t) * Hsz + ejcol] = hn;

            __threadfence();                 // release h stores (storers only)
        }
        __syncthreads();
        // ---- per-bgroup barrier: tid0 arrives; all warps poll in parallel ----
        if (tid == 0) {
            unsigned prev = atomicAdd(cnt, 1u);
            if (prev + 1u == 64u * (unsigned)(t + 1))
                atomicExch(gen, (unsigned)(t + 1));
        }
        if (lane == 0) {
            long long spins = 0;
            while (ld_acq(gen) < (unsigned)(t + 1)) {
                __nanosleep(32);
                if (++spins > 100000000LL) break;   // anti-wedge
            }
        }
        __syncwarp();
    }

    if (tid < 256)
        g_c[(bg * 32 + eb) * Hsz + ejcol] = cst;
}

// ---------------------------------------------------------------------------
// Launch 4: fused output head + final-state copy (h_t taken from g_hs[:,511])
// ---------------------------------------------------------------------------
__global__ void headfin_kernel(const float* __restrict__ Wfc, const float* __restrict__ bfc,
                               float* __restrict__ out) {
    const int blk = blockIdx.x;
    if (blk < 4096) {
        int warp = blk * 8 + ((int)threadIdx.x >> 5);
        int lane = threadIdx.x & 31;
        const float* hrow = &g_hs[(size_t)warp * Hsz];
        float acc = 0.0f;
        #pragma unroll
        for (int q = 0; q < 4; q++) {
            float4 h = *(const float4*)&hrow[q * 128 + lane * 4];
            float4 w = *(const float4*)&Wfc[q * 128 + lane * 4];
            acc += h.x * w.x + h.y * w.y + h.z * w.z + h.w * w.w;
        }
        #pragma unroll
        for (int s = 16; s > 0; s >>= 1) acc += __shfl_xor_sync(0xFFFFFFFFu, acc, s);
        if (lane == 0) out[warp] = acc + bfc[0];
    } else {
        int i = (blk - 4096) * 256 + threadIdx.x;
        #pragma unroll
        for (int r = 0; r < 2; r++) {
            int v = i * 2 + r;                  // 0..32767 = b*512 + j
            int b = v >> 9, j = v & 511;
            out[32768 + v] = g_hs[(size_t)(b * Ssz + 511) * Hsz + j];
            out[65536 + v] = g_c[v];
        }
    }
}

// ---------------------------------------------------------------------------
extern "C" void kernel_launch(void* const* d_in, const int* in_sizes, int n_in,
                              void* d_out, int out_size) {
    const float* x   = (const float*)d_in[0];
    const float* Wf  = (const float*)d_in[1];
    const float* Wi  = (const float*)d_in[2];
    const float* Wo  = (const float*)d_in[3];
    const float* Wc  = (const float*)d_in[4];
    const float* bf  = (const float*)d_in[5];
    const float* bi  = (const float*)d_in[6];
    const float* bo  = (const float*)d_in[7];
    const float* bc  = (const float*)d_in[8];
    const float* Uf  = (const float*)d_in[9];
    const float* Ui  = (const float*)d_in[10];
    const float* Uo  = (const float*)d_in[11];
    const float* Uc  = (const float*)d_in[12];
    const float* Wfc = (const float*)d_in[13];
    const float* bfc = (const float*)d_in[14];
    float* out = (float*)d_out;

    cudaFuncSetAttribute(recur_kernel, cudaFuncAttributeMaxDynamicSharedMemorySize, RN_SMEM);
    cudaFuncSetAttribute(gemm_tc_kernel, cudaFuncAttributeMaxDynamicSharedMemorySize, GT_SMEM);

    splitx_kernel<<<ROWS * Dsz / 256, 256>>>(x);                        // launch 0
    prep_kernel<<<6400, 256>>>(Wf, Wi, Wo, Wc, bf, bi, bo, bc,
                               Uf, Ui, Uo, Uc);                         // launch 1
    gemm_tc_kernel<<<dim3(GXN / 64, ROWS / 128), 256, GT_SMEM>>>();     // launch 2
    recur_kernel<<<NBLK, 512, RN_SMEM>>>();                             // launch 3 (profiled)
    headfin_kernel<<<4096 + 64, 256>>>(Wfc, bfc, out);                  // launch 4
}

// round 17
// speedup vs baseline: 1.0406x; 1.0406x over previous
#include <cuda_runtime.h>
#include <cuda_bf16.h>

typedef unsigned long long ull;

#define Bsz 64
#define Ssz 512
#define Dsz 256
#define Hsz 512
#define ROWS (Bsz * Ssz)   /* 32768 */
#define GXN  (4 * Hsz)     /* 2048  */
#define NBLK 128           /* persistent CTAs (all resident on 148 SMs) */

// ---------------------------------------------------------------------------
// Static device scratch
// ---------------------------------------------------------------------------
__device__ float g_gxq[(size_t)ROWS * GXN];   // [b*512+t][j*4+gate]
__device__ float g_hs[(size_t)ROWS * Hsz];    // [b*512+t][j]
__device__ float g_c[Bsz * Hsz];
__device__ float g_bq[GXN];
// per-bgroup barrier state (separate 128B lines)
__device__ unsigned g_cnt2[2 * 32];
__device__ unsigned g_gen2[2 * 32];
// bf16 split operands for the tensor-core input GEMM (W only; x converted in-kernel)
__device__ __nv_bfloat16 g_Wthi[(size_t)GXN * Dsz];   // [n][k] (n = j*4+gate)
__device__ __nv_bfloat16 g_Wtlo[(size_t)GXN * Dsz];
// bf16 split U for the HMMA recurrence: [jg(64)][n32(32)][k(512)], n32 = j8*4+g
__device__ __nv_bfloat16 g_Ubhi[64 * 32 * 512];
__device__ __nv_bfloat16 g_Ublo[64 * 32 * 512];
// bf16 split h, double-buffered: [buf][b(64)][j(512)]
__device__ __nv_bfloat16 g_hbhi[2][Bsz * Hsz];
__device__ __nv_bfloat16 g_hblo[2][Bsz * Hsz];

// ---------------------------------------------------------------------------
// helpers
// ---------------------------------------------------------------------------
__device__ __forceinline__ unsigned ld_acq(const unsigned* p) {
    unsigned v; asm volatile("ld.acquire.gpu.b32 %0, [%1];" : "=r"(v) : "l"(p)); return v;
}
__device__ __forceinline__ unsigned atom_add_acqrel(unsigned* p, unsigned v) {
    unsigned o;
    asm volatile("atom.add.acq_rel.gpu.u32 %0, [%1], %2;"
                 : "=r"(o) : "l"(p), "r"(v) : "memory");
    return o;
}
__device__ __forceinline__ void atom_exch_rel(unsigned* p, unsigned v) {
    unsigned o;
    asm volatile("atom.exch.release.gpu.b32 %0, [%1], %2;"
                 : "=r"(o) : "l"(p), "r"(v) : "memory");
}
__device__ __forceinline__ float sigmoidf_(float x) { return 1.0f / (1.0f + __expf(-x)); }
__device__ __forceinline__ float tanhf_(float x)    { return 1.0f - 2.0f / (__expf(2.0f * x) + 1.0f); }

__device__ __forceinline__ unsigned smem_u32(const void* p) {
    unsigned a;
    asm("{ .reg .u64 t; cvta.to.shared.u64 t, %1; cvt.u32.u64 %0, t; }" : "=r"(a) : "l"(p));
    return a;
}
__device__ __forceinline__ void ldsm4(unsigned& r0, unsigned& r1, unsigned& r2, unsigned& r3,
                                      unsigned addr) {
    asm volatile("ldmatrix.sync.aligned.m8n8.x4.shared.b16 {%0,%1,%2,%3}, [%4];"
                 : "=r"(r0), "=r"(r1), "=r"(r2), "=r"(r3) : "r"(addr));
}
__device__ __forceinline__ void ldsm2(unsigned& r0, unsigned& r1, unsigned addr) {
    asm volatile("ldmatrix.sync.aligned.m8n8.x2.shared.b16 {%0,%1}, [%2];"
                 : "=r"(r0), "=r"(r1) : "r"(addr));
}
__device__ __forceinline__ void mma_bf16(float& c0, float& c1, float& c2, float& c3,
                                         unsigned a0, unsigned a1, unsigned a2, unsigned a3,
                                         unsigned b0, unsigned b1) {
    asm volatile("mma.sync.aligned.m16n8k16.row.col.f32.bf16.bf16.f32 "
                 "{%0,%1,%2,%3}, {%4,%5,%6,%7}, {%8,%9}, {%0,%1,%2,%3};"
                 : "+f"(c0), "+f"(c1), "+f"(c2), "+f"(c3)
                 : "r"(a0), "r"(a1), "r"(a2), "r"(a3), "r"(b0), "r"(b1));
}

// ---------------------------------------------------------------------------
// Launch 0: init — zero h0 (bf16 bufs) + barrier counters
// ---------------------------------------------------------------------------
__global__ void init_kernel() {
    int i = blockIdx.x * blockDim.x + threadIdx.x;     // 0..32767
    g_hbhi[0][i] = __float2bfloat16(0.0f);
    g_hblo[0][i] = __float2bfloat16(0.0f);
    if (i < 2) { g_cnt2[i * 32] = 0u; g_gen2[i * 32] = 0u; }
}

// ---------------------------------------------------------------------------
// Launch 1: fused prep
//   blocks [0,4096):      U -> bf16 hi/lo [jg][n32][k]
//   blocks [4096,6144):   W -> transposed bf16 hi/lo + bias
// ---------------------------------------------------------------------------
__global__ void prep_kernel(const float* __restrict__ Wf, const float* __restrict__ Wi,
                            const float* __restrict__ Wo, const float* __restrict__ Wc,
                            const float* __restrict__ bf, const float* __restrict__ bi,
                            const float* __restrict__ bo, const float* __restrict__ bc,
                            const float* __restrict__ Uf, const float* __restrict__ Ui,
                            const float* __restrict__ Uo, const float* __restrict__ Uc) {
    const int blk = blockIdx.x;
    const int tid = threadIdx.x;
    if (blk < 4096) {
        int idx = blk * 256 + tid;                 // 0..1048575 = jg*32n*512k
        int k   = idx & 511;
        int n32 = (idx >> 9) & 31;
        int jg  = idx >> 14;
        int j   = jg * 8 + (n32 >> 2);
        int g   = n32 & 3;
        const float* Ug = (g == 0) ? Uf : (g == 1) ? Ui : (g == 2) ? Uo : Uc;
        float v = Ug[(size_t)k * Hsz + j];
        __nv_bfloat16 hi = __float2bfloat16(v);
        g_Ubhi[idx] = hi;
        g_Ublo[idx] = __float2bfloat16(v - __bfloat162float(hi));
    } else {
        int idx = (blk - 4096) * 256 + tid;        // 0..524287
        int n = idx >> 8;
        int k = idx & 255;
        int j = n >> 2, g = n & 3;
        const float* Wg = (g == 0) ? Wf : (g == 1) ? Wi : (g == 2) ? Wo : Wc;
        float v = Wg[(size_t)k * Hsz + j];
        __nv_bfloat16 hi = __float2bfloat16(v);
        g_Wthi[(size_t)n * Dsz + k] = hi;
        g_Wtlo[(size_t)n * Dsz + k] = __float2bfloat16(v - __bfloat162float(hi));
        if (k == 0) {
            const float* bg = (g == 0) ? bf : (g == 1) ? bi : (g == 2) ? bo : bc;
            g_bq[n] = bg[j];
        }
    }
}

// ---------------------------------------------------------------------------
// Launch 2: mma.sync bf16 split-precision input GEMM
//   (x loaded as fp32 — L2-resident — and split to hi/lo in-register; R15 form)
// ---------------------------------------------------------------------------
#define SB_ST   264
#define SA_ST   40
#define SB_HI   0
#define SB_LO   (64 * SB_ST * 2)
#define SA_HI   (2 * 64 * SB_ST * 2)
#define SA_LO   (SA_HI + 128 * SA_ST * 2)
#define GT_SMEM (SA_LO + 128 * SA_ST * 2)     /* 88064 */

__global__ void __launch_bounds__(256, 2)
gemm_tc_kernel(const float* __restrict__ x) {
    extern __shared__ char smem[];
    const unsigned sbase = smem_u32(smem);

    const int tid  = threadIdx.x;
    const int lane = tid & 31;
    const int wid  = tid >> 5;
    const int wm   = wid & 3;
    const int wn   = wid >> 2;
    const int m0w  = wm * 32;
    const int n0w  = wn * 32;
    const int n0   = blockIdx.x * 64;
    const int r0   = blockIdx.y * 128;

    #pragma unroll
    for (int r = 0; r < 8; r++) {
        int v = r * 256 + tid;
        int row = v >> 5, cu = v & 31;
        size_t src = (size_t)(n0 + row) * Dsz + cu * 8;
        *(uint4*)(smem + SB_HI + (row * SB_ST + cu * 8) * 2) = *(const uint4*)&g_Wthi[src];
        *(uint4*)(smem + SB_LO + (row * SB_ST + cu * 8) * 2) = *(const uint4*)&g_Wtlo[src];
    }

    float c[2][4][4];
    #pragma unroll
    for (int mi = 0; mi < 2; mi++)
        #pragma unroll
        for (int ni = 0; ni < 4; ni++)
            #pragma unroll
            for (int e = 0; e < 4; e++) c[mi][ni][e] = 0.0f;

    const int aRow  = lane & 15;
    const int aKoff = (lane >> 4) * 8;
    const int bSel  = lane >> 3;
    const int bRow  = (bSel >> 1) * 8 + (lane & 7);
    const int bKoff = (bSel & 1) * 8;

    for (int kc = 0; kc < 8; kc++) {
        __syncthreads();
        #pragma unroll
        for (int r = 0; r < 2; r++) {
            int v = r * 256 + tid;
            int row = v >> 2, cu = v & 3;
            const float* src = &x[(size_t)(r0 + row) * Dsz + kc * 32 + cu * 8];
            float4 f0 = *(const float4*)src;
            float4 f1 = *(const float4*)(src + 4);
            float vals[8] = {f0.x, f0.y, f0.z, f0.w, f1.x, f1.y, f1.z, f1.w};
            __nv_bfloat16 his[8], los[8];
            #pragma unroll
            for (int e = 0; e < 8; e++) {
                __nv_bfloat16 h = __float2bfloat16(vals[e]);
                his[e] = h;
                los[e] = __float2bfloat16(vals[e] - __bfloat162float(h));
            }
            *(uint4*)(smem + SA_HI + (row * SA_ST + cu * 8) * 2) = *(uint4*)his;
            *(uint4*)(smem + SA_LO + (row * SA_ST + cu * 8) * 2) = *(uint4*)los;
        }
        __syncthreads();

        #pragma unroll
        for (int ks = 0; ks < 2; ks++) {
            const int kchunk = ks * 16;
            const int kglob  = kc * 32 + kchunk;

            unsigned ah[2][4], al[2][4];
            #pragma unroll
            for (int mi = 0; mi < 2; mi++) {
                unsigned off = (unsigned)((m0w + mi * 16 + aRow) * SA_ST + kchunk + aKoff) * 2;
                ldsm4(ah[mi][0], ah[mi][1], ah[mi][2], ah[mi][3], sbase + SA_HI + off);
                ldsm4(al[mi][0], al[mi][1], al[mi][2], al[mi][3], sbase + SA_LO + off);
            }
            unsigned bh[4][2], bl[4][2];
            #pragma unroll
            for (int half = 0; half < 2; half++) {
                unsigned off = (unsigned)((n0w + half * 16 + bRow) * SB_ST + kglob + bKoff) * 2;
                ldsm4(bh[half * 2][0], bh[half * 2][1], bh[half * 2 + 1][0], bh[half * 2 + 1][1],
                      sbase + SB_HI + off);
                ldsm4(bl[half * 2][0], bl[half * 2][1], bl[half * 2 + 1][0], bl[half * 2 + 1][1],
                      sbase + SB_LO + off);
            }

            #pragma unroll
            for (int mi = 0; mi < 2; mi++)
                #pragma unroll
                for (int ni = 0; ni < 4; ni++) {
                    float* cc = c[mi][ni];
                    mma_bf16(cc[0], cc[1], cc[2], cc[3],
                             ah[mi][0], ah[mi][1], ah[mi][2], ah[mi][3],
                             bh[ni][0], bh[ni][1]);
                    mma_bf16(cc[0], cc[1], cc[2], cc[3],
                             ah[mi][0], ah[mi][1], ah[mi][2], ah[mi][3],
                             bl[ni][0], bl[ni][1]);
                    mma_bf16(cc[0], cc[1], cc[2], cc[3],
                             al[mi][0], al[mi][1], al[mi][2], al[mi][3],
                             bh[ni][0], bh[ni][1]);
                }
        }
    }

    const int crow = lane >> 2;
    const int ccol = (lane & 3) * 2;
    #pragma unroll
    for (int mi = 0; mi < 2; mi++) {
        #pragma unroll
        for (int ni = 0; ni < 4; ni++) {
            int col = n0 + n0w + ni * 8 + ccol;
            float2 bb = *(const float2*)&g_bq[col];
            int m1 = r0 + m0w + mi * 16 + crow;
            float2 o0; o0.x = c[mi][ni][0] + bb.x; o0.y = c[mi][ni][1] + bb.y;
            float2 o1; o1.x = c[mi][ni][2] + bb.x; o1.y = c[mi][ni][3] + bb.y;
            *(float2*)&g_gxq[(size_t)m1 * GXN + col] = o0;
            *(float2*)&g_gxq[(size_t)(m1 + 8) * GXN + col] = o1;
        }
    }
}

// ---------------------------------------------------------------------------
// Launch 3 (PROFILED): persistent HMMA LSTM recurrence — R15 structure with
//   the per-thread __threadfence replaced by a release-chain arrival:
//   stores -> __syncthreads -> tid0 atom.add.acq_rel (cumulative release) ->
//   last arriver atom.exch.release gen -> tid0 ld.acquire poll -> __syncthreads.
// ---------------------------------------------------------------------------
#define RN_ST    520                     /* bf16 per row (1040B stride) */
#define RN_SPLIT (32 * RN_ST * 2)        /* 33280 B per split */
#define RN_SU    0
#define RN_SH    (2 * RN_SPLIT)          /* 66560 */
#define RN_SRED  (4 * RN_SPLIT)          /* 133120 */
#define RN_RST   34                      /* f32 stride per m-row (even) */
#define RN_RSL   (32 * RN_RST)           /* 1088 floats per k-slice */
#define RN_SMEM  (RN_SRED + 4 * RN_RSL * 4)    /* 150528 */

__global__ void __launch_bounds__(512, 1)
recur_kernel() {
    extern __shared__ char smem[];
    const unsigned sbase = smem_u32(smem);
    float* sRedF = (float*)(smem + RN_SRED);

    const int tid  = threadIdx.x;
    const int lane = tid & 31;
    const int wid  = tid >> 5;
    const int ng   = wid & 3;            // n-group (8 n cols)
    const int ksl  = wid >> 2;           // k-slice (128 k)
    const int jg   = blockIdx.x >> 1;
    const int bg   = blockIdx.x & 1;

    unsigned* cnt = &g_cnt2[bg * 32];
    unsigned* gen = &g_gen2[bg * 32];

    // ---- load U slice (bf16 hi/lo) into SMEM once ----
    {
        const __nv_bfloat16* uh = &g_Ubhi[jg * 32 * 512];
        const __nv_bfloat16* ul = &g_Ublo[jg * 32 * 512];
        #pragma unroll
        for (int r = 0; r < 8; r++) {
            int v = r * 512 + tid;               // 0..4095 uint4 (both splits)
            int split = v >> 11;
            int w = v & 2047;
            int n = w >> 6, k8 = w & 63;
            const __nv_bfloat16* src = split ? ul : uh;
            *(uint4*)(smem + RN_SU + split * RN_SPLIT + n * (RN_ST * 2) + k8 * 16) =
                *(const uint4*)&src[n * 512 + k8 * 8];
        }
    }

    const int aRow  = lane & 15;
    const int aKoff = (lane >> 4) * 8;
    const int bRow  = lane & 7;
    const int bKoff = ((lane >> 3) & 1) * 8;

    const int eb  = tid & 31;
    const int ej8 = (tid >> 5) & 7;
    const int ejcol = jg * 8 + ej8;
    float cst = 0.0f;

    for (int t = 0; t < Ssz; t++) {
        const int rd = t & 1, wr = rd ^ 1;

        float4 gx;
        if (tid < 256)
            gx = *(const float4*)
                &g_gxq[(size_t)((bg * 32 + eb) * Ssz + t) * GXN + ejcol * 4];

        // ---- stage h (bf16 hi/lo) rows [bg*32, bg*32+32) ----
        {
            const __nv_bfloat16* hh = g_hbhi[rd];
            const __nv_bfloat16* hl = g_hblo[rd];
            #pragma unroll
            for (int r = 0; r < 8; r++) {
                int v = r * 512 + tid;
                int split = v >> 11;
                int w = v & 2047;
                int row = w >> 6, k8 = w & 63;
                const __nv_bfloat16* src = split ? hl : hh;
                uint4 d = __ldcg((const uint4*)&src[(bg * 32 + row) * Hsz + k8 * 8]);
                *(uint4*)(smem + RN_SH + split * RN_SPLIT + row * (RN_ST * 2) + k8 * 16) = d;
            }
        }
        __syncthreads();

        // ---- HMMA compute ----
        float c[2][4];
        #pragma unroll
        for (int mi = 0; mi < 2; mi++)
            #pragma unroll
            for (int e = 0; e < 4; e++) c[mi][e] = 0.0f;

        const int kbase = ksl * 128;
        #pragma unroll 2
        for (int kf = 0; kf < 8; kf++) {
            const int k = kbase + kf * 16;
            unsigned ah[2][4], al[2][4];
            #pragma unroll
            for (int mi = 0; mi < 2; mi++) {
                unsigned off = (unsigned)((mi * 16 + aRow) * (RN_ST * 2) + (k + aKoff) * 2);
                ldsm4(ah[mi][0], ah[mi][1], ah[mi][2], ah[mi][3],
                      sbase + RN_SH + off);
                ldsm4(al[mi][0], al[mi][1], al[mi][2], al[mi][3],
                      sbase + RN_SH + RN_SPLIT + off);
            }
            unsigned bh[2], bl[2];
            {
                unsigned off = (unsigned)((ng * 8 + bRow) * (RN_ST * 2) + (k + bKoff) * 2);
                ldsm2(bh[0], bh[1], sbase + RN_SU + off);
                ldsm2(bl[0], bl[1], sbase + RN_SU + RN_SPLIT + off);
            }
            #pragma unroll
            for (int mi = 0; mi < 2; mi++) {
                mma_bf16(c[mi][0], c[mi][1], c[mi][2], c[mi][3],
                         ah[mi][0], ah[mi][1], ah[mi][2], ah[mi][3], bh[0], bh[1]);
                mma_bf16(c[mi][0], c[mi][1], c[mi][2], c[mi][3],
                         ah[mi][0], ah[mi][1], ah[mi][2], ah[mi][3], bl[0], bl[1]);
                mma_bf16(c[mi][0], c[mi][1], c[mi][2], c[mi][3],
                         al[mi][0], al[mi][1], al[mi][2], al[mi][3], bh[0], bh[1]);
            }
        }

        // ---- write partials to sRed[ksl][m][RN_RST] ----
        {
            const int col = ng * 8 + (lane & 3) * 2;
            #pragma unroll
            for (int mi = 0; mi < 2; mi++) {
                int m = mi * 16 + (lane >> 2);
                float2 p0; p0.x = c[mi][0]; p0.y = c[mi][1];
                float2 p1; p1.x = c[mi][2]; p1.y = c[mi][3];
                *(float2*)&sRedF[ksl * RN_RSL + m * RN_RST + col]       = p0;
                *(float2*)&sRedF[ksl * RN_RSL + (m + 8) * RN_RST + col] = p1;
            }
        }
        __syncthreads();

        // ---- epilogue: 256 threads, one (b,j) cell each (no per-thread fence) ----
        if (tid < 256) {
            float s[4];
            #pragma unroll
            for (int g = 0; g < 4; g++) {
                int cix = eb * RN_RST + ej8 * 4 + g;
                s[g] = sRedF[cix] + sRedF[RN_RSL + cix]
                     + sRedF[2 * RN_RSL + cix] + sRedF[3 * RN_RSL + cix];
            }
            float pf = gx.x + s[0];
            float pi = gx.y + s[1];
            float po = gx.z + s[2];
            float pc = gx.w + s[3];

            cst = sigmoidf_(pf) * cst + sigmoidf_(pi) * tanhf_(pc);
            float hn = sigmoidf_(po) * tanhf_(cst);

            int bglob = bg * 32 + eb;
            __nv_bfloat16 hhi = __float2bfloat16(hn);
            g_hbhi[wr][bglob * Hsz + ejcol] = hhi;
            g_hblo[wr][bglob * Hsz + ejcol] =
                __float2bfloat16(hn - __bfloat162float(hhi));
            g_hs[(size_t)(bglob * Ssz + t) * Hsz + ejcol] = hn;
        }
        __syncthreads();
        // ---- per-bgroup barrier: release-chain arrival, tid0 poll (R15 mechanics) ----
        if (tid == 0) {
            unsigned prev = atom_add_acqrel(cnt, 1u);      // cumulative release of h stores
            if (prev + 1u == 64u * (unsigned)(t + 1)) {
                atom_exch_rel(gen, (unsigned)(t + 1));
            } else {
                long long spins = 0;
                while (ld_acq(gen) < (unsigned)(t + 1)) {
                    __nanosleep(64);
                    if (++spins > 100000000LL) break;      // anti-wedge
                }
            }
        }
        __syncthreads();
    }

    if (tid < 256)
        g_c[(bg * 32 + eb) * Hsz + ejcol] = cst;
}

// ---------------------------------------------------------------------------
// Launch 4: fused output head + final-state copy (h_t taken from g_hs[:,511])
// ---------------------------------------------------------------------------
__global__ void headfin_kernel(const float* __restrict__ Wfc, const float* __restrict__ bfc,
                               float* __restrict__ out) {
    const int blk = blockIdx.x;
    if (blk < 4096) {
        int warp = blk * 8 + ((int)threadIdx.x >> 5);
        int lane = threadIdx.x & 31;
        const float* hrow = &g_hs[(size_t)warp * Hsz];
        float acc = 0.0f;
        #pragma unroll
        for (int q = 0; q < 4; q++) {
            float4 h = *(const float4*)&hrow[q * 128 + lane * 4];
            float4 w = *(const float4*)&Wfc[q * 128 + lane * 4];
            acc += h.x * w.x + h.y * w.y + h.z * w.z + h.w * w.w;
        }
        #pragma unroll
        for (int s = 16; s > 0; s >>= 1) acc += __shfl_xor_sync(0xFFFFFFFFu, acc, s);
        if (lane == 0) out[warp] = acc + bfc[0];
    } else {
        int i = (blk - 4096) * 256 + threadIdx.x;
        #pragma unroll
        for (int r = 0; r < 2; r++) {
            int v = i * 2 + r;                  // 0..32767 = b*512 + j
            int b = v >> 9, j = v & 511;
            out[32768 + v] = g_hs[(size_t)(b * Ssz + 511) * Hsz + j];
            out[65536 + v] = g_c[v];
        }
    }
}

// ---------------------------------------------------------------------------
extern "C" void kernel_launch(void* const* d_in, const int* in_sizes, int n_in,
                              void* d_out, int out_size) {
    const float* x   = (const float*)d_in[0];
    const float* Wf  = (const float*)d_in[1];
    const float* Wi  = (const float*)d_in[2];
    const float* Wo  = (const float*)d_in[3];
    const float* Wc  = (const float*)d_in[4];
    const float* bf  = (const float*)d_in[5];
    const float* bi  = (const float*)d_in[6];
    const float* bo  = (const float*)d_in[7];
    const float* bc  = (const float*)d_in[8];
    const float* Uf  = (const float*)d_in[9];
    const float* Ui  = (const float*)d_in[10];
    const float* Uo  = (const float*)d_in[11];
    const float* Uc  = (const float*)d_in[12];
    const float* Wfc = (const float*)d_in[13];
    const float* bfc = (const float*)d_in[14];
    float* out = (float*)d_out;

    cudaFuncSetAttribute(recur_kernel, cudaFuncAttributeMaxDynamicSharedMemorySize, RN_SMEM);
    cudaFuncSetAttribute(gemm_tc_kernel, cudaFuncAttributeMaxDynamicSharedMemorySize, GT_SMEM);

    init_kernel<<<128, 256>>>();                                        // launch 0
    prep_kernel<<<6144, 256>>>(Wf, Wi, Wo, Wc, bf, bi, bo, bc,
                               Uf, Ui, Uo, Uc);                         // launch 1
    gemm_tc_kernel<<<dim3(GXN / 64, ROWS / 128), 256, GT_SMEM>>>(x);    // launch 2
    recur_kernel<<<NBLK, 512, RN_SMEM>>>();                             // launch 3 (profiled)
    headfin_kernel<<<4096 + 64, 256>>>(Wfc, bfc, out);                  // launch 4
}